// round 2
// baseline (speedup 1.0000x reference)
#include <cuda_runtime.h>
#include <math.h>

#define Bdim 16
#define Ldim 4096
#define Cdim 256
#define Ddim 512
#define EPSF 1e-8f

// ------------------- scratch (device globals; no allocs allowed) -------------------
__device__ float g_feats[(size_t)Bdim * Ddim * Ldim];   // [b][d=512][l]
__device__ float g_attn[(size_t)Bdim * 4 * Ldim];       // [b][i][l]
__device__ float g_wT[589824];                          // transposed weights

#define OFF_PWT 0        // [4][256][128]
#define OFF_W1T 131072   // [512][128]
#define OFF_FWT 196608   // [512][512]
#define OFF_RWT 458752   // [256][512]
#define WT_TOTAL 589824

// ------------------- helpers -------------------
template <int BS>
__device__ __forceinline__ void gemm_step(const float* __restrict__ A,
                                          const float* __restrict__ Bm,
                                          int ty, int tx, float acc[8][8]) {
    #pragma unroll 4
    for (int kk = 0; kk < 32; kk++) {
        const float* ar = A + kk * 128 + ty * 8;
        const float* br = Bm + kk * BS + tx * 8;
        float4 a0 = *(const float4*)ar;
        float4 a1 = *(const float4*)(ar + 4);
        float4 b0 = *(const float4*)br;
        float4 b1 = *(const float4*)(br + 4);
        float av[8] = {a0.x, a0.y, a0.z, a0.w, a1.x, a1.y, a1.z, a1.w};
        float bv[8] = {b0.x, b0.y, b0.z, b0.w, b1.x, b1.y, b1.z, b1.w};
        #pragma unroll
        for (int i = 0; i < 8; i++)
            #pragma unroll
            for (int j = 0; j < 8; j++)
                acc[i][j] += av[i] * bv[j];
    }
}

// ------------------- K0: weight transposes -------------------
__global__ void k_prep(const float* __restrict__ pw1, const float* __restrict__ pw3,
                       const float* __restrict__ pw5, const float* __restrict__ pw7,
                       const float* __restrict__ w1, const float* __restrict__ fw,
                       const float* __restrict__ rw) {
    int idx = blockIdx.x * blockDim.x + threadIdx.x;
    if (idx >= WT_TOTAL) return;
    float v;
    if (idx < OFF_W1T) {                     // pwT[s][c][o] = pw_s[o][c]
        int s = idx >> 15;
        int r = idx & 32767;
        int c = r >> 7, o = r & 127;
        const float* pw = (s == 0) ? pw1 : (s == 1) ? pw3 : (s == 2) ? pw5 : pw7;
        v = pw[o * Cdim + c];
    } else if (idx < OFF_FWT) {              // w1T[c][o] = w1[o][c]
        int r = idx - OFF_W1T;
        int c = r >> 7, o = r & 127;
        v = w1[o * Ddim + c];
    } else if (idx < OFF_RWT) {              // fwT[c][o] = fw[o][c]
        int r = idx - OFF_FWT;
        int c = r >> 9, o = r & 511;
        v = fw[o * Ddim + c];
    } else {                                 // rwT[c][o] = rw[o][c]
        int r = idx - OFF_RWT;
        int c = r >> 9, o = r & 511;
        v = rw[o * Cdim + c];
    }
    g_wT[idx] = v;
}

// ------------------- K1: depthwise conv + pointwise + channel RMSNorm + GELU -------------------
__global__ __launch_bounds__(256) void k_conv(
    const float* __restrict__ x,
    const float* __restrict__ dw1, const float* __restrict__ dw3,
    const float* __restrict__ dw5, const float* __restrict__ dw7,
    const float* __restrict__ cn1, const float* __restrict__ cn3,
    const float* __restrict__ cn5, const float* __restrict__ cn7) {
    __shared__ float xs[4288];          // union: xs[134][32]  /  ws[32][128]
    __shared__ float hs[32 * 132];      // conv output [c][l], padded
    __shared__ float red[128 * 17];     // rms reduction

    int tid = threadIdx.x;
    int lt = blockIdx.x, b = blockIdx.y, sc = blockIdx.z;
    int l0 = lt * 128;
    int k = 2 * sc + 1;                 // 1,3,5,7
    int r = sc;                          // k/2
    const float* dw = (sc == 0) ? dw1 : (sc == 1) ? dw3 : (sc == 2) ? dw5 : dw7;
    const float* cn = (sc == 0) ? cn1 : (sc == 1) ? cn3 : (sc == 2) ? cn5 : cn7;
    const float* pwT = g_wT + OFF_PWT + sc * 32768;

    float acc[8][8];
    #pragma unroll
    for (int i = 0; i < 8; i++)
        #pragma unroll
        for (int j = 0; j < 8; j++) acc[i][j] = 0.f;

    int cld = tid & 31, lg = tid >> 5;      // staging/conv coords
    int ogw = tid & 127, kk0 = tid >> 7;    // ws staging coords
    int tx = tid & 15, ty = tid >> 4;       // micro-tile coords

    for (int c0 = 0; c0 < Cdim; c0 += 32) {
        // stage x rows [l0-3, l0+131) x 32 channels
        for (int i = lg; i < 134; i += 8) {
            int gl = l0 - 3 + i;
            float v = 0.f;
            if (gl >= 0 && gl < Ldim)
                v = x[((size_t)b * Ldim + gl) * Cdim + c0 + cld];
            xs[i * 32 + cld] = v;
        }
        __syncthreads();
        // depthwise conv -> hs[c][l]
        float rd[7];
        #pragma unroll
        for (int t = 0; t < 7; t++) rd[t] = (t < k) ? dw[(c0 + cld) * k + t] : 0.f;
        #pragma unroll
        for (int ii = 0; ii < 16; ii++) {
            int l = lg * 16 + ii;
            float s = 0.f;
            for (int t = 0; t < k; t++) s += rd[t] * xs[(l + 3 - r + t) * 32 + cld];
            hs[cld * 132 + l] = s;
        }
        __syncthreads();
        // stage pw chunk over xs
        for (int kk = kk0; kk < 32; kk += 2)
            xs[kk * 128 + ogw] = pwT[(c0 + kk) * 128 + ogw];
        __syncthreads();
        gemm_step<132>(xs, hs, ty, tx, acc);
        __syncthreads();
    }

    // epilogue: channel RMSNorm over 128 outputs + cn scale + exact GELU
    #pragma unroll
    for (int j = 0; j < 8; j++) {
        float p = 0.f;
        #pragma unroll
        for (int i = 0; i < 8; i++) p += acc[i][j] * acc[i][j];
        red[(tx * 8 + j) * 17 + ty] = p;
    }
    __syncthreads();
    float inv[8];
    #pragma unroll
    for (int j = 0; j < 8; j++) {
        float s = 0.f;
        #pragma unroll
        for (int t = 0; t < 16; t++) s += red[(tx * 8 + j) * 17 + t];
        float rms = sqrtf(s * (1.f / 128.f));
        inv[j] = 1.f / (rms + EPSF);
    }
    float cnv[8];
    #pragma unroll
    for (int i = 0; i < 8; i++) cnv[i] = cn[ty * 8 + i];
    #pragma unroll
    for (int i = 0; i < 8; i++) {
        float v[8];
        #pragma unroll
        for (int j = 0; j < 8; j++) {
            float h = acc[i][j] * cnv[i] * inv[j];
            v[j] = h * normcdff(h);   // exact gelu
        }
        size_t base = ((size_t)b * Ddim + sc * 128 + ty * 8 + i) * Ldim + l0 + tx * 8;
        *(float4*)(g_feats + base) = make_float4(v[0], v[1], v[2], v[3]);
        *(float4*)(g_feats + base + 4) = make_float4(v[4], v[5], v[6], v[7]);
    }
}

// ------------------- K2: attention MLP + softmax -------------------
__global__ __launch_bounds__(256) void k_attn(const float* __restrict__ b1p,
                                              const float* __restrict__ w2p,
                                              const float* __restrict__ b2p) {
    __shared__ float ws[32 * 128];
    __shared__ float fs[32 * 128];
    __shared__ float red[128 * 17];
    __shared__ float w2s[512];

    int tid = threadIdx.x;
    int b = blockIdx.y;
    int l0 = blockIdx.x * 128;
    const float* w1T = g_wT + OFF_W1T;

    w2s[tid] = w2p[tid];
    w2s[tid + 256] = w2p[tid + 256];

    float acc[8][8];
    #pragma unroll
    for (int i = 0; i < 8; i++)
        #pragma unroll
        for (int j = 0; j < 8; j++) acc[i][j] = 0.f;

    int lw = tid & 127, kk0 = tid >> 7;
    int tx = tid & 15, ty = tid >> 4;

    for (int c0 = 0; c0 < 512; c0 += 32) {
        for (int kk = kk0; kk < 32; kk += 2) {
            ws[kk * 128 + lw] = w1T[(c0 + kk) * 128 + lw];
            fs[kk * 128 + lw] = g_feats[((size_t)b * Ddim + c0 + kk) * Ldim + l0 + lw];
        }
        __syncthreads();
        gemm_step<128>(ws, fs, ty, tx, acc);
        __syncthreads();
    }

    // bias + exact gelu
    float b1v[8];
    #pragma unroll
    for (int i = 0; i < 8; i++) b1v[i] = b1p[ty * 8 + i];
    #pragma unroll
    for (int i = 0; i < 8; i++)
        #pragma unroll
        for (int j = 0; j < 8; j++) {
            float h = acc[i][j] + b1v[i];
            acc[i][j] = h * normcdff(h);
        }

    // w2 reduce -> a2[4][8]
    float a2[4][8];
    for (int i4 = 0; i4 < 4; i4++) {
        float wv[8];
        #pragma unroll
        for (int i = 0; i < 8; i++) wv[i] = w2s[i4 * 128 + ty * 8 + i];
        #pragma unroll
        for (int j = 0; j < 8; j++) {
            float p = 0.f;
            #pragma unroll
            for (int i = 0; i < 8; i++) p += wv[i] * acc[i][j];
            red[(tx * 8 + j) * 17 + ty] = p;
        }
        __syncthreads();
        float b2v = b2p[i4];
        #pragma unroll
        for (int j = 0; j < 8; j++) {
            float s = 0.f;
            #pragma unroll
            for (int t = 0; t < 16; t++) s += red[(tx * 8 + j) * 17 + t];
            a2[i4][j] = s + b2v;
        }
        __syncthreads();
    }

    // softmax over 4 scales per l
    #pragma unroll
    for (int j = 0; j < 8; j++) {
        float m = fmaxf(fmaxf(a2[0][j], a2[1][j]), fmaxf(a2[2][j], a2[3][j]));
        float s = 0.f;
        #pragma unroll
        for (int i4 = 0; i4 < 4; i4++) {
            a2[i4][j] = expf(a2[i4][j] - m);
            s += a2[i4][j];
        }
        float invs = 1.f / s;
        #pragma unroll
        for (int i4 = 0; i4 < 4; i4++) a2[i4][j] *= invs;
    }
    if (ty == 0) {
        #pragma unroll
        for (int i4 = 0; i4 < 4; i4++) {
            size_t base = ((size_t)b * 4 + i4) * Ldim + l0 + tx * 8;
            *(float4*)(g_attn + base) = make_float4(a2[i4][0], a2[i4][1], a2[i4][2], a2[i4][3]);
            *(float4*)(g_attn + base + 4) = make_float4(a2[i4][4], a2[i4][5], a2[i4][6], a2[i4][7]);
        }
    }
}

// ------------------- K3: final GEMM (feats*attn || x) + residual, pre-norm -------------------
__global__ __launch_bounds__(256) void k_final(const float* __restrict__ x,
                                               float* __restrict__ out) {
    __shared__ float ws[32 * 128];
    __shared__ float cs[32 * 132];
    __shared__ float am[512];

    int tid = threadIdx.x;
    int lt = blockIdx.x, ot = blockIdx.y, b = blockIdx.z;
    int l0 = lt * 128, o0 = ot * 128;

    am[tid]       = g_attn[((size_t)b * 4 + (tid >> 7)) * Ldim + l0 + (tid & 127)];
    am[tid + 256] = g_attn[((size_t)b * 4 + 2 + (tid >> 7)) * Ldim + l0 + (tid & 127)];
    __syncthreads();

    float acc[8][8];
    #pragma unroll
    for (int i = 0; i < 8; i++)
        #pragma unroll
        for (int j = 0; j < 8; j++) acc[i][j] = 0.f;

    int lw = tid & 127, kk0 = tid >> 7;
    int tx = tid & 15, ty = tid >> 4;
    int cld = tid & 31, lg = tid >> 5;
    const float* fwT = g_wT + OFF_FWT;
    const float* rwT = g_wT + OFF_RWT;

    // phase 1: combined = feats * attn
    for (int c0 = 0; c0 < 512; c0 += 32) {
        int sc = c0 >> 7;
        for (int kk = kk0; kk < 32; kk += 2) {
            ws[kk * 128 + lw] = fwT[(c0 + kk) * 512 + o0 + lw];
            cs[kk * 132 + lw] = g_feats[((size_t)b * Ddim + c0 + kk) * Ldim + l0 + lw] * am[sc * 128 + lw];
        }
        __syncthreads();
        gemm_step<132>(ws, cs, ty, tx, acc);
        __syncthreads();
    }
    // phase 2: residual = res_w @ x
    for (int c0 = 0; c0 < 256; c0 += 32) {
        for (int kk = kk0; kk < 32; kk += 2)
            ws[kk * 128 + lw] = rwT[(c0 + kk) * 512 + o0 + lw];
        for (int lr = lg; lr < 128; lr += 8)
            cs[cld * 132 + lr] = x[((size_t)b * Ldim + l0 + lr) * Cdim + c0 + cld];
        __syncthreads();
        gemm_step<132>(ws, cs, ty, tx, acc);
        __syncthreads();
    }

    // store transposed to [b][l][o]
    #pragma unroll
    for (int j = 0; j < 8; j++) {
        size_t base = ((size_t)b * Ldim + l0 + tx * 8 + j) * Ddim + o0 + ty * 8;
        *(float4*)(out + base)     = make_float4(acc[0][j], acc[1][j], acc[2][j], acc[3][j]);
        *(float4*)(out + base + 4) = make_float4(acc[4][j], acc[5][j], acc[6][j], acc[7][j]);
    }
}

// ------------------- K4: final row RMSNorm (in place) -------------------
__global__ __launch_bounds__(256) void k_norm(float* __restrict__ out,
                                              const float* __restrict__ nsc) {
    __shared__ float ns[512];
    int tid = threadIdx.x;
    ns[tid] = nsc[tid];
    ns[tid + 256] = nsc[tid + 256];
    __syncthreads();

    int warp = tid >> 5, lane = tid & 31;
    size_t row = (size_t)blockIdx.x * 8 + warp;
    float* p = out + row * Ddim;

    float4 v[4];
    float ssq = 0.f;
    #pragma unroll
    for (int q = 0; q < 4; q++) {
        v[q] = *(const float4*)(p + (q * 32 + lane) * 4);
        ssq += v[q].x * v[q].x + v[q].y * v[q].y + v[q].z * v[q].z + v[q].w * v[q].w;
    }
    #pragma unroll
    for (int off = 16; off > 0; off >>= 1)
        ssq += __shfl_xor_sync(0xFFFFFFFFu, ssq, off);
    float rms = sqrtf(ssq * (1.f / 512.f));
    float inv = 1.f / (rms + EPSF);
    #pragma unroll
    for (int q = 0; q < 4; q++) {
        int base = (q * 32 + lane) * 4;
        float4 w;
        w.x = v[q].x * ns[base + 0] * inv;
        w.y = v[q].y * ns[base + 1] * inv;
        w.z = v[q].z * ns[base + 2] * inv;
        w.w = v[q].w * ns[base + 3] * inv;
        *(float4*)(p + base) = w;
    }
}

// ------------------- launch -------------------
extern "C" void kernel_launch(void* const* d_in, const int* in_sizes, int n_in,
                              void* d_out, int out_size) {
    const float* x = (const float*)d_in[0];
    const float *dw[4], *pw[4], *cnp[4];
    if (in_sizes[2] == 768) {   // signature order: x, dw1,dw3,dw5,dw7, pw1.., cn1..
        for (int i = 0; i < 4; i++) {
            dw[i]  = (const float*)d_in[1 + i];
            pw[i]  = (const float*)d_in[5 + i];
            cnp[i] = (const float*)d_in[9 + i];
        }
    } else {                     // dict order: x, (dw,pw,cn) per scale
        for (int i = 0; i < 4; i++) {
            dw[i]  = (const float*)d_in[1 + 3 * i];
            pw[i]  = (const float*)d_in[2 + 3 * i];
            cnp[i] = (const float*)d_in[3 + 3 * i];
        }
    }
    const float* w1  = (const float*)d_in[13];
    const float* b1  = (const float*)d_in[14];
    const float* w2  = (const float*)d_in[15];
    const float* b2  = (const float*)d_in[16];
    const float* fw  = (const float*)d_in[17];
    const float* nsc = (const float*)d_in[18];
    const float* rw  = (const float*)d_in[19];
    float* out = (float*)d_out;

    k_prep<<<WT_TOTAL / 256, 256>>>(pw[0], pw[1], pw[2], pw[3], w1, fw, rw);
    k_conv<<<dim3(Ldim / 128, Bdim, 4), 256>>>(x, dw[0], dw[1], dw[2], dw[3],
                                               cnp[0], cnp[1], cnp[2], cnp[3]);
    k_attn<<<dim3(Ldim / 128, Bdim), 256>>>(b1, w2, b2);
    k_final<<<dim3(Ldim / 128, 4, Bdim), 256>>>(x, out);
    k_norm<<<(Bdim * Ldim) / 8, 256>>>(out, nsc);
}

// round 3
// speedup vs baseline: 1.2193x; 1.2193x over previous
#include <cuda_runtime.h>
#include <math.h>

#define Bdim 16
#define Ldim 4096
#define Cdim 256
#define Ddim 512
#define EPSF 1e-8f

typedef unsigned long long ull;

// ------------------- scratch (device globals; no allocs allowed) -------------------
__device__ float g_feats[(size_t)Bdim * Ddim * Ldim];   // [b][d=512][l]
__device__ float g_attn[(size_t)Bdim * 4 * Ldim];       // [b][i][l]
__device__ float g_wT[589824];                          // transposed weights

#define OFF_PWT 0        // [4][256][128]
#define OFF_W1T 131072   // [512][128]
#define OFF_FWT 196608   // [512][512]
#define OFF_RWT 458752   // [256][512]
#define WT_TOTAL 589824

// ------------------- packed f32x2 helpers -------------------
__device__ __forceinline__ ull pk2(float x) {
    ull r; asm("mov.b64 %0, {%1, %1};" : "=l"(r) : "f"(x)); return r;
}
__device__ __forceinline__ void fma2(ull& c, ull a, ull b) {
    asm("fma.rn.f32x2 %0, %1, %2, %0;" : "+l"(c) : "l"(a), "l"(b));
}
__device__ __forceinline__ float2 up2(ull v) {
    float2 f; asm("mov.b64 {%0, %1}, %2;" : "=f"(f.x), "=f"(f.y) : "l"(v)); return f;
}

// 8x8 micro-tile GEMM step over a 32-deep k-chunk, f32x2-packed along j.
template <int BS>
__device__ __forceinline__ void gemm_step2(const float* __restrict__ A,
                                           const float* __restrict__ Bm,
                                           int ty, int tx, ull acc[8][4]) {
    #pragma unroll 4
    for (int kk = 0; kk < 32; kk++) {
        const float* ar = A + kk * 128 + ty * 8;
        const float* br = Bm + kk * BS + tx * 8;
        float4 a0 = *(const float4*)ar;
        float4 a1 = *(const float4*)(ar + 4);
        ulonglong2 bb0 = *(const ulonglong2*)br;
        ulonglong2 bb1 = *(const ulonglong2*)(br + 4);
        ull bp[4] = {bb0.x, bb0.y, bb1.x, bb1.y};
        float av[8] = {a0.x, a0.y, a0.z, a0.w, a1.x, a1.y, a1.z, a1.w};
        #pragma unroll
        for (int i = 0; i < 8; i++) {
            ull ai = pk2(av[i]);
            #pragma unroll
            for (int j2 = 0; j2 < 4; j2++) fma2(acc[i][j2], ai, bp[j2]);
        }
    }
}

__device__ __forceinline__ void unpack_acc(const ull a[8][4], float f[8][8]) {
    #pragma unroll
    for (int i = 0; i < 8; i++)
        #pragma unroll
        for (int j2 = 0; j2 < 4; j2++) {
            float2 p = up2(a[i][j2]);
            f[i][2 * j2] = p.x;
            f[i][2 * j2 + 1] = p.y;
        }
}

// ------------------- K0: weight transposes -------------------
__global__ void k_prep(const float* __restrict__ pw1, const float* __restrict__ pw3,
                       const float* __restrict__ pw5, const float* __restrict__ pw7,
                       const float* __restrict__ w1, const float* __restrict__ fw,
                       const float* __restrict__ rw) {
    int idx = blockIdx.x * blockDim.x + threadIdx.x;
    if (idx >= WT_TOTAL) return;
    float v;
    if (idx < OFF_W1T) {                     // pwT[s][c][o] = pw_s[o][c]
        int s = idx >> 15;
        int r = idx & 32767;
        int c = r >> 7, o = r & 127;
        const float* pw = (s == 0) ? pw1 : (s == 1) ? pw3 : (s == 2) ? pw5 : pw7;
        v = pw[o * Cdim + c];
    } else if (idx < OFF_FWT) {              // w1T[c][o] = w1[o][c]
        int r = idx - OFF_W1T;
        int c = r >> 7, o = r & 127;
        v = w1[o * Ddim + c];
    } else if (idx < OFF_RWT) {              // fwT[c][o] = fw[o][c]
        int r = idx - OFF_FWT;
        int c = r >> 9, o = r & 511;
        v = fw[o * Ddim + c];
    } else {                                 // rwT[c][o] = rw[o][c]
        int r = idx - OFF_RWT;
        int c = r >> 9, o = r & 511;
        v = rw[o * Cdim + c];
    }
    g_wT[idx] = v;
}

// ------------------- K1: depthwise conv + pointwise + channel RMSNorm + GELU -------------------
__global__ __launch_bounds__(256) void k_conv(
    const float* __restrict__ x,
    const float* __restrict__ dw1, const float* __restrict__ dw3,
    const float* __restrict__ dw5, const float* __restrict__ dw7,
    const float* __restrict__ cn1, const float* __restrict__ cn3,
    const float* __restrict__ cn5, const float* __restrict__ cn7) {
    __shared__ float xs[4288];          // union: xs[134][32]  /  ws[32][128]
    __shared__ float hs[32 * 132];      // conv output [c][l], padded
    __shared__ float red[128 * 17];     // rms reduction

    int tid = threadIdx.x;
    int lt = blockIdx.x, b = blockIdx.y, sc = blockIdx.z;
    int l0 = lt * 128;
    int k = 2 * sc + 1;                 // 1,3,5,7
    int r = sc;                          // k/2
    const float* dw = (sc == 0) ? dw1 : (sc == 1) ? dw3 : (sc == 2) ? dw5 : dw7;
    const float* cn = (sc == 0) ? cn1 : (sc == 1) ? cn3 : (sc == 2) ? cn5 : cn7;
    const float* pwT = g_wT + OFF_PWT + sc * 32768;

    ull acc[8][4];
    #pragma unroll
    for (int i = 0; i < 8; i++)
        #pragma unroll
        for (int j = 0; j < 4; j++) acc[i][j] = 0ull;

    int cld = tid & 31, lg = tid >> 5;      // staging/conv coords
    int ogw = tid & 127, kk0 = tid >> 7;    // ws staging coords
    int tx = tid & 15, ty = tid >> 4;       // micro-tile coords

    for (int c0 = 0; c0 < Cdim; c0 += 32) {
        // stage x rows [l0-3, l0+131) x 32 channels
        for (int i = lg; i < 134; i += 8) {
            int gl = l0 - 3 + i;
            float v = 0.f;
            if (gl >= 0 && gl < Ldim)
                v = x[((size_t)b * Ldim + gl) * Cdim + c0 + cld];
            xs[i * 32 + cld] = v;
        }
        __syncthreads();
        // depthwise conv -> hs[c][l]
        float rd[7];
        #pragma unroll
        for (int t = 0; t < 7; t++) rd[t] = (t < k) ? dw[(c0 + cld) * k + t] : 0.f;
        #pragma unroll
        for (int ii = 0; ii < 16; ii++) {
            int l = lg * 16 + ii;
            float s = 0.f;
            for (int t = 0; t < k; t++) s += rd[t] * xs[(l + 3 - r + t) * 32 + cld];
            hs[cld * 132 + l] = s;
        }
        __syncthreads();
        // stage pw chunk over xs
        for (int kk = kk0; kk < 32; kk += 2)
            xs[kk * 128 + ogw] = pwT[(c0 + kk) * 128 + ogw];
        __syncthreads();
        gemm_step2<132>(xs, hs, ty, tx, acc);
        __syncthreads();
    }

    float accf[8][8];
    unpack_acc(acc, accf);

    // epilogue: channel RMSNorm over 128 outputs + cn scale + exact GELU
    #pragma unroll
    for (int j = 0; j < 8; j++) {
        float p = 0.f;
        #pragma unroll
        for (int i = 0; i < 8; i++) p += accf[i][j] * accf[i][j];
        red[(tx * 8 + j) * 17 + ty] = p;
    }
    __syncthreads();
    float inv[8];
    #pragma unroll
    for (int j = 0; j < 8; j++) {
        float s = 0.f;
        #pragma unroll
        for (int t = 0; t < 16; t++) s += red[(tx * 8 + j) * 17 + t];
        float rms = sqrtf(s * (1.f / 128.f));
        inv[j] = 1.f / (rms + EPSF);
    }
    float cnv[8];
    #pragma unroll
    for (int i = 0; i < 8; i++) cnv[i] = cn[ty * 8 + i];
    #pragma unroll
    for (int i = 0; i < 8; i++) {
        float v[8];
        #pragma unroll
        for (int j = 0; j < 8; j++) {
            float h = accf[i][j] * cnv[i] * inv[j];
            v[j] = h * normcdff(h);   // exact gelu
        }
        size_t base = ((size_t)b * Ddim + sc * 128 + ty * 8 + i) * Ldim + l0 + tx * 8;
        *(float4*)(g_feats + base) = make_float4(v[0], v[1], v[2], v[3]);
        *(float4*)(g_feats + base + 4) = make_float4(v[4], v[5], v[6], v[7]);
    }
}

// ------------------- K2: attention MLP + softmax -------------------
__global__ __launch_bounds__(256) void k_attn(const float* __restrict__ b1p,
                                              const float* __restrict__ w2p,
                                              const float* __restrict__ b2p) {
    __shared__ float ws[32 * 128];
    __shared__ float fs[32 * 128];
    __shared__ float red[128 * 17];
    __shared__ float w2s[512];

    int tid = threadIdx.x;
    int b = blockIdx.y;
    int l0 = blockIdx.x * 128;
    const float* w1T = g_wT + OFF_W1T;

    w2s[tid] = w2p[tid];
    w2s[tid + 256] = w2p[tid + 256];

    ull acc[8][4];
    #pragma unroll
    for (int i = 0; i < 8; i++)
        #pragma unroll
        for (int j = 0; j < 4; j++) acc[i][j] = 0ull;

    int lw = tid & 127, kk0 = tid >> 7;
    int tx = tid & 15, ty = tid >> 4;

    for (int c0 = 0; c0 < 512; c0 += 32) {
        for (int kk = kk0; kk < 32; kk += 2) {
            ws[kk * 128 + lw] = w1T[(c0 + kk) * 128 + lw];
            fs[kk * 128 + lw] = g_feats[((size_t)b * Ddim + c0 + kk) * Ldim + l0 + lw];
        }
        __syncthreads();
        gemm_step2<128>(ws, fs, ty, tx, acc);
        __syncthreads();
    }

    float accf[8][8];
    unpack_acc(acc, accf);

    // bias + exact gelu
    float b1v[8];
    #pragma unroll
    for (int i = 0; i < 8; i++) b1v[i] = b1p[ty * 8 + i];
    #pragma unroll
    for (int i = 0; i < 8; i++)
        #pragma unroll
        for (int j = 0; j < 8; j++) {
            float h = accf[i][j] + b1v[i];
            accf[i][j] = h * normcdff(h);
        }

    // w2 reduce -> a2[4][8]
    float a2[4][8];
    for (int i4 = 0; i4 < 4; i4++) {
        float wv[8];
        #pragma unroll
        for (int i = 0; i < 8; i++) wv[i] = w2s[i4 * 128 + ty * 8 + i];
        #pragma unroll
        for (int j = 0; j < 8; j++) {
            float p = 0.f;
            #pragma unroll
            for (int i = 0; i < 8; i++) p += wv[i] * accf[i][j];
            red[(tx * 8 + j) * 17 + ty] = p;
        }
        __syncthreads();
        float b2v = b2p[i4];
        #pragma unroll
        for (int j = 0; j < 8; j++) {
            float s = 0.f;
            #pragma unroll
            for (int t = 0; t < 16; t++) s += red[(tx * 8 + j) * 17 + t];
            a2[i4][j] = s + b2v;
        }
        __syncthreads();
    }

    // softmax over 4 scales per l
    #pragma unroll
    for (int j = 0; j < 8; j++) {
        float m = fmaxf(fmaxf(a2[0][j], a2[1][j]), fmaxf(a2[2][j], a2[3][j]));
        float s = 0.f;
        #pragma unroll
        for (int i4 = 0; i4 < 4; i4++) {
            a2[i4][j] = expf(a2[i4][j] - m);
            s += a2[i4][j];
        }
        float invs = 1.f / s;
        #pragma unroll
        for (int i4 = 0; i4 < 4; i4++) a2[i4][j] *= invs;
    }
    if (ty == 0) {
        #pragma unroll
        for (int i4 = 0; i4 < 4; i4++) {
            size_t base = ((size_t)b * 4 + i4) * Ldim + l0 + tx * 8;
            *(float4*)(g_attn + base) = make_float4(a2[i4][0], a2[i4][1], a2[i4][2], a2[i4][3]);
            *(float4*)(g_attn + base + 4) = make_float4(a2[i4][4], a2[i4][5], a2[i4][6], a2[i4][7]);
        }
    }
}

// ------------------- K3: final GEMM (feats*attn || x) + residual, pre-norm -------------------
__global__ __launch_bounds__(256) void k_final(const float* __restrict__ x,
                                               float* __restrict__ out) {
    __shared__ float ws[32 * 128];
    __shared__ float cs[32 * 132];
    __shared__ float am[512];

    int tid = threadIdx.x;
    int lt = blockIdx.x, ot = blockIdx.y, b = blockIdx.z;
    int l0 = lt * 128, o0 = ot * 128;

    am[tid]       = g_attn[((size_t)b * 4 + (tid >> 7)) * Ldim + l0 + (tid & 127)];
    am[tid + 256] = g_attn[((size_t)b * 4 + 2 + (tid >> 7)) * Ldim + l0 + (tid & 127)];
    __syncthreads();

    ull acc[8][4];
    #pragma unroll
    for (int i = 0; i < 8; i++)
        #pragma unroll
        for (int j = 0; j < 4; j++) acc[i][j] = 0ull;

    int lw = tid & 127, kk0 = tid >> 7;
    int tx = tid & 15, ty = tid >> 4;
    int cld = tid & 31, lg = tid >> 5;
    const float* fwT = g_wT + OFF_FWT;
    const float* rwT = g_wT + OFF_RWT;

    // phase 1: combined = feats * attn
    for (int c0 = 0; c0 < 512; c0 += 32) {
        int sc = c0 >> 7;
        for (int kk = kk0; kk < 32; kk += 2) {
            ws[kk * 128 + lw] = fwT[(c0 + kk) * 512 + o0 + lw];
            cs[kk * 132 + lw] = g_feats[((size_t)b * Ddim + c0 + kk) * Ldim + l0 + lw] * am[sc * 128 + lw];
        }
        __syncthreads();
        gemm_step2<132>(ws, cs, ty, tx, acc);
        __syncthreads();
    }
    // phase 2: residual = res_w @ x
    for (int c0 = 0; c0 < 256; c0 += 32) {
        for (int kk = kk0; kk < 32; kk += 2)
            ws[kk * 128 + lw] = rwT[(c0 + kk) * 512 + o0 + lw];
        for (int lr = lg; lr < 128; lr += 8)
            cs[cld * 132 + lr] = x[((size_t)b * Ldim + l0 + lr) * Cdim + c0 + cld];
        __syncthreads();
        gemm_step2<132>(ws, cs, ty, tx, acc);
        __syncthreads();
    }

    float accf[8][8];
    unpack_acc(acc, accf);

    // store transposed to [b][l][o]
    #pragma unroll
    for (int j = 0; j < 8; j++) {
        size_t base = ((size_t)b * Ldim + l0 + tx * 8 + j) * Ddim + o0 + ty * 8;
        *(float4*)(out + base)     = make_float4(accf[0][j], accf[1][j], accf[2][j], accf[3][j]);
        *(float4*)(out + base + 4) = make_float4(accf[4][j], accf[5][j], accf[6][j], accf[7][j]);
    }
}

// ------------------- K4: final row RMSNorm (in place) -------------------
__global__ __launch_bounds__(256) void k_norm(float* __restrict__ out,
                                              const float* __restrict__ nsc) {
    __shared__ float ns[512];
    int tid = threadIdx.x;
    ns[tid] = nsc[tid];
    ns[tid + 256] = nsc[tid + 256];
    __syncthreads();

    int warp = tid >> 5, lane = tid & 31;
    size_t row = (size_t)blockIdx.x * 8 + warp;
    float* p = out + row * Ddim;

    float4 v[4];
    float ssq = 0.f;
    #pragma unroll
    for (int q = 0; q < 4; q++) {
        v[q] = *(const float4*)(p + (q * 32 + lane) * 4);
        ssq += v[q].x * v[q].x + v[q].y * v[q].y + v[q].z * v[q].z + v[q].w * v[q].w;
    }
    #pragma unroll
    for (int off = 16; off > 0; off >>= 1)
        ssq += __shfl_xor_sync(0xFFFFFFFFu, ssq, off);
    float rms = sqrtf(ssq * (1.f / 512.f));
    float inv = 1.f / (rms + EPSF);
    #pragma unroll
    for (int q = 0; q < 4; q++) {
        int base = (q * 32 + lane) * 4;
        float4 w;
        w.x = v[q].x * ns[base + 0] * inv;
        w.y = v[q].y * ns[base + 1] * inv;
        w.z = v[q].z * ns[base + 2] * inv;
        w.w = v[q].w * ns[base + 3] * inv;
        *(float4*)(p + base) = w;
    }
}

// ------------------- launch -------------------
extern "C" void kernel_launch(void* const* d_in, const int* in_sizes, int n_in,
                              void* d_out, int out_size) {
    const float* x = (const float*)d_in[0];
    const float *dw[4], *pw[4], *cnp[4];
    if (in_sizes[2] == 768) {   // signature order: x, dw1,dw3,dw5,dw7, pw1.., cn1..
        for (int i = 0; i < 4; i++) {
            dw[i]  = (const float*)d_in[1 + i];
            pw[i]  = (const float*)d_in[5 + i];
            cnp[i] = (const float*)d_in[9 + i];
        }
    } else {                     // dict order: x, (dw,pw,cn) per scale
        for (int i = 0; i < 4; i++) {
            dw[i]  = (const float*)d_in[1 + 3 * i];
            pw[i]  = (const float*)d_in[2 + 3 * i];
            cnp[i] = (const float*)d_in[3 + 3 * i];
        }
    }
    const float* w1  = (const float*)d_in[13];
    const float* b1  = (const float*)d_in[14];
    const float* w2  = (const float*)d_in[15];
    const float* b2  = (const float*)d_in[16];
    const float* fw  = (const float*)d_in[17];
    const float* nsc = (const float*)d_in[18];
    const float* rw  = (const float*)d_in[19];
    float* out = (float*)d_out;

    k_prep<<<WT_TOTAL / 256, 256>>>(pw[0], pw[1], pw[2], pw[3], w1, fw, rw);
    k_conv<<<dim3(Ldim / 128, Bdim, 4), 256>>>(x, dw[0], dw[1], dw[2], dw[3],
                                               cnp[0], cnp[1], cnp[2], cnp[3]);
    k_attn<<<dim3(Ldim / 128, Bdim), 256>>>(b1, w2, b2);
    k_final<<<dim3(Ldim / 128, 4, Bdim), 256>>>(x, out);
    k_norm<<<(Bdim * Ldim) / 8, 256>>>(out, nsc);
}

// round 4
// speedup vs baseline: 1.4332x; 1.1755x over previous
#include <cuda_runtime.h>
#include <math.h>

#define Bdim 16
#define Ldim 4096
#define Cdim 256
#define Ddim 512
#define EPSF 1e-8f

typedef unsigned long long ull;

// ------------------- scratch (device globals; no allocs allowed) -------------------
__device__ float g_feats[(size_t)Bdim * Ddim * Ldim];   // [b][d=512][l]
__device__ float g_attn[(size_t)Bdim * 4 * Ldim];       // [b][i][l]
__device__ float g_wT[589824];                          // transposed weights

#define OFF_PWT 0        // [4][256][128]
#define OFF_W1T 131072   // [512][128]
#define OFF_FWT 196608   // [512][512]
#define OFF_RWT 458752   // [256][512]
#define WT_TOTAL 589824

// ------------------- packed f32x2 + cp.async helpers -------------------
__device__ __forceinline__ ull pk2(float x) {
    ull r; asm("mov.b64 %0, {%1, %1};" : "=l"(r) : "f"(x)); return r;
}
__device__ __forceinline__ void fma2(ull& c, ull a, ull b) {
    asm("fma.rn.f32x2 %0, %1, %2, %0;" : "+l"(c) : "l"(a), "l"(b));
}
__device__ __forceinline__ float2 up2(ull v) {
    float2 f; asm("mov.b64 {%0, %1}, %2;" : "=f"(f.x), "=f"(f.y) : "l"(v)); return f;
}
__device__ __forceinline__ void cpa16(float* dst, const float* src) {
    unsigned s = (unsigned)__cvta_generic_to_shared(dst);
    asm volatile("cp.async.cg.shared.global [%0], [%1], 16;" :: "r"(s), "l"(src));
}
#define CP_COMMIT() asm volatile("cp.async.commit_group;")
#define CP_WAIT0()  asm volatile("cp.async.wait_group 0;" ::: "memory")

// 8x8 micro-tile GEMM step over a 32-deep k-chunk, f32x2-packed along j.
template <int BS>
__device__ __forceinline__ void gemm_step2(const float* __restrict__ A,
                                           const float* __restrict__ Bm,
                                           int ty, int tx, ull acc[8][4]) {
    #pragma unroll 4
    for (int kk = 0; kk < 32; kk++) {
        const float* ar = A + kk * 128 + ty * 8;
        const float* br = Bm + kk * BS + tx * 8;
        float4 a0 = *(const float4*)ar;
        float4 a1 = *(const float4*)(ar + 4);
        ulonglong2 bb0 = *(const ulonglong2*)br;
        ulonglong2 bb1 = *(const ulonglong2*)(br + 4);
        ull bp[4] = {bb0.x, bb0.y, bb1.x, bb1.y};
        float av[8] = {a0.x, a0.y, a0.z, a0.w, a1.x, a1.y, a1.z, a1.w};
        #pragma unroll
        for (int i = 0; i < 8; i++) {
            ull ai = pk2(av[i]);
            #pragma unroll
            for (int j2 = 0; j2 < 4; j2++) fma2(acc[i][j2], ai, bp[j2]);
        }
    }
}

__device__ __forceinline__ void unpack_acc(const ull a[8][4], float f[8][8]) {
    #pragma unroll
    for (int i = 0; i < 8; i++)
        #pragma unroll
        for (int j2 = 0; j2 < 4; j2++) {
            float2 p = up2(a[i][j2]);
            f[i][2 * j2] = p.x;
            f[i][2 * j2 + 1] = p.y;
        }
}

// warp-shape remap: warp footprint = 4 ty x 8 tx  (cuts LDS wavefronts 6 -> 4 per kk)
#define TILE_COORDS(tid, tx, ty)                         \
    int lane_ = (tid) & 31, warp_ = (tid) >> 5;          \
    int tx = ((warp_ & 1) << 3) | (lane_ & 7);           \
    int ty = ((warp_ >> 1) << 2) | (lane_ >> 3);

// ------------------- K0: weight transposes -------------------
__global__ void k_prep(const float* __restrict__ pw1, const float* __restrict__ pw3,
                       const float* __restrict__ pw5, const float* __restrict__ pw7,
                       const float* __restrict__ w1, const float* __restrict__ fw,
                       const float* __restrict__ rw) {
    int idx = blockIdx.x * blockDim.x + threadIdx.x;
    if (idx >= WT_TOTAL) return;
    float v;
    if (idx < OFF_W1T) {
        int s = idx >> 15;
        int r = idx & 32767;
        int c = r >> 7, o = r & 127;
        const float* pw = (s == 0) ? pw1 : (s == 1) ? pw3 : (s == 2) ? pw5 : pw7;
        v = pw[o * Cdim + c];
    } else if (idx < OFF_FWT) {
        int r = idx - OFF_W1T;
        int c = r >> 7, o = r & 127;
        v = w1[o * Ddim + c];
    } else if (idx < OFF_RWT) {
        int r = idx - OFF_FWT;
        int c = r >> 9, o = r & 511;
        v = fw[o * Ddim + c];
    } else {
        int r = idx - OFF_RWT;
        int c = r >> 9, o = r & 511;
        v = rw[o * Cdim + c];
    }
    g_wT[idx] = v;
}

// ------------------- K1: depthwise conv + pointwise + channel RMSNorm + GELU -------------------
// dyn smem: xs[4288] | hs[4224] | ws[2][4096] | red[2176]   = 75520 B
__global__ __launch_bounds__(256, 2) void k_conv(
    const float* __restrict__ x,
    const float* __restrict__ dw1, const float* __restrict__ dw3,
    const float* __restrict__ dw5, const float* __restrict__ dw7,
    const float* __restrict__ cn1, const float* __restrict__ cn3,
    const float* __restrict__ cn5, const float* __restrict__ cn7) {
    extern __shared__ float sm[];
    float* xs  = sm;                 // [134][32]
    float* hs  = sm + 4288;          // [32][132]
    float* ws0 = sm + 8512;
    float* ws1 = sm + 12608;
    float* red = sm + 16704;         // [128][17]

    int tid = threadIdx.x;
    int lt = blockIdx.x, b = blockIdx.y, sc = blockIdx.z;
    int l0 = lt * 128;
    int k = 2 * sc + 1;
    int r = sc;
    const float* dw = (sc == 0) ? dw1 : (sc == 1) ? dw3 : (sc == 2) ? dw5 : dw7;
    const float* cn = (sc == 0) ? cn1 : (sc == 1) ? cn3 : (sc == 2) ? cn5 : cn7;
    const float* pwT = g_wT + OFF_PWT + sc * 32768;

    ull acc[8][4];
    #pragma unroll
    for (int i = 0; i < 8; i++)
        #pragma unroll
        for (int j = 0; j < 4; j++) acc[i][j] = 0ull;

    int cld = tid & 31, lg = tid >> 5;
    TILE_COORDS(tid, tx, ty);

    float xr[17];
    // prefetch chunk 0
    #pragma unroll
    for (int q = 0; q < 17; q++) {
        int i = lg + 8 * q;
        if (i < 134) {
            int gl = l0 - 3 + i;
            xr[q] = (gl >= 0 && gl < Ldim) ? x[((size_t)b * Ldim + gl) * Cdim + cld] : 0.f;
        }
    }
    #pragma unroll
    for (int q = 0; q < 4; q++) {
        int idx = q * 256 + tid, kk = idx >> 5, seg = (idx & 31) << 2;
        cpa16(ws0 + kk * 128 + seg, pwT + (size_t)kk * 128 + seg);
    }
    CP_COMMIT();

    for (int c0 = 0, ci = 0; c0 < Cdim; c0 += 32, ci++) {
        float* wsc = (ci & 1) ? ws1 : ws0;
        float* wsn = (ci & 1) ? ws0 : ws1;
        CP_WAIT0();
        #pragma unroll
        for (int q = 0; q < 17; q++) {
            int i = lg + 8 * q;
            if (i < 134) xs[i * 32 + cld] = xr[q];
        }
        __syncthreads();
        // depthwise conv -> hs[c][l]
        float rd[7];
        #pragma unroll
        for (int t = 0; t < 7; t++) rd[t] = (t < k) ? dw[(c0 + cld) * k + t] : 0.f;
        #pragma unroll
        for (int ii = 0; ii < 16; ii++) {
            int l = lg * 16 + ii;
            float s = 0.f;
            for (int t = 0; t < k; t++) s += rd[t] * xs[(l + 3 - r + t) * 32 + cld];
            hs[cld * 132 + l] = s;
        }
        // prefetch next chunk during gemm
        if (c0 + 32 < Cdim) {
            #pragma unroll
            for (int q = 0; q < 17; q++) {
                int i = lg + 8 * q;
                if (i < 134) {
                    int gl = l0 - 3 + i;
                    xr[q] = (gl >= 0 && gl < Ldim)
                          ? x[((size_t)b * Ldim + gl) * Cdim + c0 + 32 + cld] : 0.f;
                }
            }
            #pragma unroll
            for (int q = 0; q < 4; q++) {
                int idx = q * 256 + tid, kk = idx >> 5, seg = (idx & 31) << 2;
                cpa16(wsn + kk * 128 + seg, pwT + (size_t)(c0 + 32 + kk) * 128 + seg);
            }
            CP_COMMIT();
        }
        __syncthreads();
        gemm_step2<132>(wsc, hs, ty, tx, acc);
        __syncthreads();
    }

    float accf[8][8];
    unpack_acc(acc, accf);

    // epilogue: channel RMSNorm over 128 outputs + cn scale + exact GELU
    #pragma unroll
    for (int j = 0; j < 8; j++) {
        float p = 0.f;
        #pragma unroll
        for (int i = 0; i < 8; i++) p += accf[i][j] * accf[i][j];
        red[(tx * 8 + j) * 17 + ty] = p;
    }
    __syncthreads();
    float inv[8];
    #pragma unroll
    for (int j = 0; j < 8; j++) {
        float s = 0.f;
        #pragma unroll
        for (int t = 0; t < 16; t++) s += red[(tx * 8 + j) * 17 + t];
        float rms = sqrtf(s * (1.f / 128.f));
        inv[j] = 1.f / (rms + EPSF);
    }
    float cnv[8];
    #pragma unroll
    for (int i = 0; i < 8; i++) cnv[i] = cn[ty * 8 + i];
    #pragma unroll
    for (int i = 0; i < 8; i++) {
        float v[8];
        #pragma unroll
        for (int j = 0; j < 8; j++) {
            float h = accf[i][j] * cnv[i] * inv[j];
            v[j] = h * normcdff(h);
        }
        size_t base = ((size_t)b * Ddim + sc * 128 + ty * 8 + i) * Ldim + l0 + tx * 8;
        *(float4*)(g_feats + base) = make_float4(v[0], v[1], v[2], v[3]);
        *(float4*)(g_feats + base + 4) = make_float4(v[4], v[5], v[6], v[7]);
    }
}

// ------------------- K2: attention MLP + softmax -------------------
// dyn smem: ws[2][4096] | fs[2][4096] | red[2176] | w2s[512] = 76288 B
__global__ __launch_bounds__(256, 2) void k_attn(const float* __restrict__ b1p,
                                                 const float* __restrict__ w2p,
                                                 const float* __restrict__ b2p) {
    extern __shared__ float sm[];
    float* ws0 = sm;
    float* ws1 = sm + 4096;
    float* fs0 = sm + 8192;
    float* fs1 = sm + 12288;
    float* red = sm + 16384;
    float* w2s = sm + 18560;

    int tid = threadIdx.x;
    int b = blockIdx.y;
    int l0 = blockIdx.x * 128;
    const float* w1T = g_wT + OFF_W1T;

    w2s[tid] = w2p[tid];
    w2s[tid + 256] = w2p[tid + 256];

    ull acc[8][4];
    #pragma unroll
    for (int i = 0; i < 8; i++)
        #pragma unroll
        for (int j = 0; j < 4; j++) acc[i][j] = 0ull;

    TILE_COORDS(tid, tx, ty);

    // stage chunk 0
    #pragma unroll
    for (int q = 0; q < 4; q++) {
        int idx = q * 256 + tid, kk = idx >> 5, seg = (idx & 31) << 2;
        cpa16(ws0 + kk * 128 + seg, w1T + (size_t)kk * 128 + seg);
        cpa16(fs0 + kk * 128 + seg, g_feats + ((size_t)b * Ddim + kk) * Ldim + l0 + seg);
    }
    CP_COMMIT();

    for (int ci = 0; ci < 16; ci++) {
        float* wsc = (ci & 1) ? ws1 : ws0;
        float* fsc = (ci & 1) ? fs1 : fs0;
        CP_WAIT0();
        __syncthreads();
        if (ci < 15) {
            float* wsn = (ci & 1) ? ws0 : ws1;
            float* fsn = (ci & 1) ? fs0 : fs1;
            int c0 = (ci + 1) * 32;
            #pragma unroll
            for (int q = 0; q < 4; q++) {
                int idx = q * 256 + tid, kk = idx >> 5, seg = (idx & 31) << 2;
                cpa16(wsn + kk * 128 + seg, w1T + (size_t)(c0 + kk) * 128 + seg);
                cpa16(fsn + kk * 128 + seg, g_feats + ((size_t)b * Ddim + c0 + kk) * Ldim + l0 + seg);
            }
            CP_COMMIT();
        }
        gemm_step2<128>(wsc, fsc, ty, tx, acc);
    }
    __syncthreads();

    float accf[8][8];
    unpack_acc(acc, accf);

    float b1v[8];
    #pragma unroll
    for (int i = 0; i < 8; i++) b1v[i] = b1p[ty * 8 + i];
    #pragma unroll
    for (int i = 0; i < 8; i++)
        #pragma unroll
        for (int j = 0; j < 8; j++) {
            float h = accf[i][j] + b1v[i];
            accf[i][j] = h * normcdff(h);
        }

    float a2[4][8];
    for (int i4 = 0; i4 < 4; i4++) {
        float wv[8];
        #pragma unroll
        for (int i = 0; i < 8; i++) wv[i] = w2s[i4 * 128 + ty * 8 + i];
        #pragma unroll
        for (int j = 0; j < 8; j++) {
            float p = 0.f;
            #pragma unroll
            for (int i = 0; i < 8; i++) p += wv[i] * accf[i][j];
            red[(tx * 8 + j) * 17 + ty] = p;
        }
        __syncthreads();
        float b2v = b2p[i4];
        #pragma unroll
        for (int j = 0; j < 8; j++) {
            float s = 0.f;
            #pragma unroll
            for (int t = 0; t < 16; t++) s += red[(tx * 8 + j) * 17 + t];
            a2[i4][j] = s + b2v;
        }
        __syncthreads();
    }

    #pragma unroll
    for (int j = 0; j < 8; j++) {
        float m = fmaxf(fmaxf(a2[0][j], a2[1][j]), fmaxf(a2[2][j], a2[3][j]));
        float s = 0.f;
        #pragma unroll
        for (int i4 = 0; i4 < 4; i4++) {
            a2[i4][j] = expf(a2[i4][j] - m);
            s += a2[i4][j];
        }
        float invs = 1.f / s;
        #pragma unroll
        for (int i4 = 0; i4 < 4; i4++) a2[i4][j] *= invs;
    }
    if (ty == 0) {
        #pragma unroll
        for (int i4 = 0; i4 < 4; i4++) {
            size_t base = ((size_t)b * 4 + i4) * Ldim + l0 + tx * 8;
            *(float4*)(g_attn + base) = make_float4(a2[i4][0], a2[i4][1], a2[i4][2], a2[i4][3]);
            *(float4*)(g_attn + base + 4) = make_float4(a2[i4][4], a2[i4][5], a2[i4][6], a2[i4][7]);
        }
    }
}

// ------------------- K3: final GEMM (feats*attn || x) + residual, pre-norm -------------------
// dyn smem: ws[2][4096] | cs[4224] | am[512] = 51712 B
__global__ __launch_bounds__(256, 2) void k_final(const float* __restrict__ x,
                                                  float* __restrict__ out) {
    extern __shared__ float sm[];
    float* ws0 = sm;
    float* ws1 = sm + 4096;
    float* cs  = sm + 8192;   // [32][132]
    float* am  = sm + 12416;  // [4][128]

    int tid = threadIdx.x;
    int lt = blockIdx.x, ot = blockIdx.y, b = blockIdx.z;
    int l0 = lt * 128, o0 = ot * 128;

    am[tid]       = g_attn[((size_t)b * 4 + (tid >> 7)) * Ldim + l0 + (tid & 127)];
    am[tid + 256] = g_attn[((size_t)b * 4 + 2 + (tid >> 7)) * Ldim + l0 + (tid & 127)];

    ull acc[8][4];
    #pragma unroll
    for (int i = 0; i < 8; i++)
        #pragma unroll
        for (int j = 0; j < 4; j++) acc[i][j] = 0ull;

    int lw = tid & 127, kk0 = tid >> 7;
    int cld = tid & 31, lg = tid >> 5;
    TILE_COORDS(tid, tx, ty);
    const float* fwT = g_wT + OFF_FWT;
    const float* rwT = g_wT + OFF_RWT;

    float rg[16];
    // prefetch chunk 0 (phase 1)
    #pragma unroll
    for (int q = 0; q < 16; q++) {
        int kk = kk0 + 2 * q;
        rg[q] = g_feats[((size_t)b * Ddim + kk) * Ldim + l0 + lw];
    }
    #pragma unroll
    for (int q = 0; q < 4; q++) {
        int idx = q * 256 + tid, kk = idx >> 5, seg = (idx & 31) << 2;
        cpa16(ws0 + kk * 128 + seg, fwT + (size_t)kk * 512 + o0 + seg);
    }
    CP_COMMIT();
    __syncthreads();   // am visible

    for (int ci = 0; ci < 24; ci++) {
        float* wsc = (ci & 1) ? ws1 : ws0;
        CP_WAIT0();
        // STS current chunk
        if (ci < 16) {
            float amv = am[(ci >> 2) * 128 + lw];
            #pragma unroll
            for (int q = 0; q < 16; q++) cs[(kk0 + 2 * q) * 132 + lw] = rg[q] * amv;
        } else {
            #pragma unroll
            for (int q = 0; q < 16; q++) cs[cld * 132 + lg + 8 * q] = rg[q];
        }
        __syncthreads();
        // prefetch next chunk
        if (ci < 23) {
            int cn = ci + 1;
            if (cn < 16) {
                #pragma unroll
                for (int q = 0; q < 16; q++) {
                    int kk = kk0 + 2 * q;
                    rg[q] = g_feats[((size_t)b * Ddim + cn * 32 + kk) * Ldim + l0 + lw];
                }
            } else {
                #pragma unroll
                for (int q = 0; q < 16; q++) {
                    int lr = lg + 8 * q;
                    rg[q] = x[((size_t)b * Ldim + l0 + lr) * Cdim + (cn - 16) * 32 + cld];
                }
            }
            float* wsn = (ci & 1) ? ws0 : ws1;
            const float* srcb = (cn < 16) ? fwT + (size_t)cn * 32 * 512
                                          : rwT + (size_t)(cn - 16) * 32 * 512;
            #pragma unroll
            for (int q = 0; q < 4; q++) {
                int idx = q * 256 + tid, kk = idx >> 5, seg = (idx & 31) << 2;
                cpa16(wsn + kk * 128 + seg, srcb + (size_t)kk * 512 + o0 + seg);
            }
            CP_COMMIT();
        }
        gemm_step2<132>(wsc, cs, ty, tx, acc);
        __syncthreads();
    }

    float accf[8][8];
    unpack_acc(acc, accf);

    #pragma unroll
    for (int j = 0; j < 8; j++) {
        size_t base = ((size_t)b * Ldim + l0 + tx * 8 + j) * Ddim + o0 + ty * 8;
        *(float4*)(out + base)     = make_float4(accf[0][j], accf[1][j], accf[2][j], accf[3][j]);
        *(float4*)(out + base + 4) = make_float4(accf[4][j], accf[5][j], accf[6][j], accf[7][j]);
    }
}

// ------------------- K4: final row RMSNorm (in place) -------------------
__global__ __launch_bounds__(256) void k_norm(float* __restrict__ out,
                                              const float* __restrict__ nsc) {
    __shared__ float ns[512];
    int tid = threadIdx.x;
    ns[tid] = nsc[tid];
    ns[tid + 256] = nsc[tid + 256];
    __syncthreads();

    int warp = tid >> 5, lane = tid & 31;
    size_t row = (size_t)blockIdx.x * 8 + warp;
    float* p = out + row * Ddim;

    float4 v[4];
    float ssq = 0.f;
    #pragma unroll
    for (int q = 0; q < 4; q++) {
        v[q] = *(const float4*)(p + (q * 32 + lane) * 4);
        ssq += v[q].x * v[q].x + v[q].y * v[q].y + v[q].z * v[q].z + v[q].w * v[q].w;
    }
    #pragma unroll
    for (int off = 16; off > 0; off >>= 1)
        ssq += __shfl_xor_sync(0xFFFFFFFFu, ssq, off);
    float rms = sqrtf(ssq * (1.f / 512.f));
    float inv = 1.f / (rms + EPSF);
    #pragma unroll
    for (int q = 0; q < 4; q++) {
        int base = (q * 32 + lane) * 4;
        float4 w;
        w.x = v[q].x * ns[base + 0] * inv;
        w.y = v[q].y * ns[base + 1] * inv;
        w.z = v[q].z * ns[base + 2] * inv;
        w.w = v[q].w * ns[base + 3] * inv;
        *(float4*)(p + base) = w;
    }
}

// ------------------- launch -------------------
extern "C" void kernel_launch(void* const* d_in, const int* in_sizes, int n_in,
                              void* d_out, int out_size) {
    const float* x = (const float*)d_in[0];
    const float *dw[4], *pw[4], *cnp[4];
    if (in_sizes[2] == 768) {
        for (int i = 0; i < 4; i++) {
            dw[i]  = (const float*)d_in[1 + i];
            pw[i]  = (const float*)d_in[5 + i];
            cnp[i] = (const float*)d_in[9 + i];
        }
    } else {
        for (int i = 0; i < 4; i++) {
            dw[i]  = (const float*)d_in[1 + 3 * i];
            pw[i]  = (const float*)d_in[2 + 3 * i];
            cnp[i] = (const float*)d_in[3 + 3 * i];
        }
    }
    const float* w1  = (const float*)d_in[13];
    const float* b1  = (const float*)d_in[14];
    const float* w2  = (const float*)d_in[15];
    const float* b2  = (const float*)d_in[16];
    const float* fw  = (const float*)d_in[17];
    const float* nsc = (const float*)d_in[18];
    const float* rw  = (const float*)d_in[19];
    float* out = (float*)d_out;

    const int SM_CONV  = 75520;
    const int SM_ATTN  = 76288;
    const int SM_FINAL = 51712;
    cudaFuncSetAttribute(k_conv,  cudaFuncAttributeMaxDynamicSharedMemorySize, SM_CONV);
    cudaFuncSetAttribute(k_attn,  cudaFuncAttributeMaxDynamicSharedMemorySize, SM_ATTN);
    cudaFuncSetAttribute(k_final, cudaFuncAttributeMaxDynamicSharedMemorySize, SM_FINAL);

    k_prep<<<WT_TOTAL / 256, 256>>>(pw[0], pw[1], pw[2], pw[3], w1, fw, rw);
    k_conv<<<dim3(Ldim / 128, Bdim, 4), 256, SM_CONV>>>(x, dw[0], dw[1], dw[2], dw[3],
                                                        cnp[0], cnp[1], cnp[2], cnp[3]);
    k_attn<<<dim3(Ldim / 128, Bdim), 256, SM_ATTN>>>(b1, w2, b2);
    k_final<<<dim3(Ldim / 128, 4, Bdim), 256, SM_FINAL>>>(x, out);
    k_norm<<<(Bdim * Ldim) / 8, 256>>>(out, nsc);
}